// round 5
// baseline (speedup 1.0000x reference)
#include <cuda_runtime.h>
#include <cstdint>
#include <math.h>

#define NNODES 100000
#define NEDGES 1600000
#define KDIM   128

// ---------------- device scratch (no allocations allowed) ----------------
__device__ int   g_deg[NNODES];
__device__ int   g_rowstart[NNODES];
__device__ int   g_cursor[NNODES];
__device__ float g_invdeg[NNODES];
__device__ int   g_blocksum[128];
__device__ int   g_blockoff[128];
__device__ int   g_csr[NEDGES];
__device__ float g_yl[(size_t)NNODES * 128];
__device__ float g_yr[(size_t)NNODES * 128];
__device__ float g_h1[(size_t)NNODES * 128];
__device__ float g_h2[(size_t)NNODES * 128];

// ---------------- CSR build ----------------
__global__ void zero_deg_kernel() {
    int i = blockIdx.x * blockDim.x + threadIdx.x;
    if (i < NNODES) g_deg[i] = 0;
}

__global__ void count_deg_kernel(const int* __restrict__ dst) {
    int i = blockIdx.x * blockDim.x + threadIdx.x;
    if (i < NEDGES) atomicAdd(&g_deg[dst[i]], 1);
}

// block scans 1024 elems (256 thr x 4); writes inclusive partials into g_rowstart,
// block total into g_blocksum.
__global__ void scan1_kernel() {
    __shared__ int sdata[256];
    int b = blockIdx.x, t = threadIdx.x;
    int base = b * 1024 + t * 4;
    int v0 = (base + 0 < NNODES) ? g_deg[base + 0] : 0;
    int v1 = (base + 1 < NNODES) ? g_deg[base + 1] : 0;
    int v2 = (base + 2 < NNODES) ? g_deg[base + 2] : 0;
    int v3 = (base + 3 < NNODES) ? g_deg[base + 3] : 0;
    int tsum = v0 + v1 + v2 + v3;
    sdata[t] = tsum;
    __syncthreads();
    for (int off = 1; off < 256; off <<= 1) {
        int x = (t >= off) ? sdata[t - off] : 0;
        __syncthreads();
        sdata[t] += x;
        __syncthreads();
    }
    int excl = sdata[t] - tsum;
    int r0 = excl + v0, r1 = r0 + v1, r2 = r1 + v2, r3 = r2 + v3;
    if (base + 0 < NNODES) g_rowstart[base + 0] = r0;
    if (base + 1 < NNODES) g_rowstart[base + 1] = r1;
    if (base + 2 < NNODES) g_rowstart[base + 2] = r2;
    if (base + 3 < NNODES) g_rowstart[base + 3] = r3;
    if (t == 255) g_blocksum[b] = sdata[255];
}

__global__ void scan2_kernel(int nb) {
    __shared__ int sdata[128];
    int t = threadIdx.x;
    int v = (t < nb) ? g_blocksum[t] : 0;
    sdata[t] = v;
    __syncthreads();
    for (int off = 1; off < 128; off <<= 1) {
        int x = (t >= off) ? sdata[t - off] : 0;
        __syncthreads();
        sdata[t] += x;
        __syncthreads();
    }
    g_blockoff[t] = sdata[t] - v;   // exclusive
}

__global__ void scan3_kernel() {
    int i = blockIdx.x * blockDim.x + threadIdx.x;
    if (i >= NNODES) return;
    int incl = g_rowstart[i];
    int d = g_deg[i];
    int start = incl - d + g_blockoff[i >> 10];
    g_rowstart[i] = start;
    g_cursor[i] = start;
    g_invdeg[i] = 1.0f / (float)max(d, 1);
}

__global__ void fill_csr_kernel(const int* __restrict__ src, const int* __restrict__ dst) {
    int i = blockIdx.x * blockDim.x + threadIdx.x;
    if (i >= NEDGES) return;
    int d = dst[i];
    int p = atomicAdd(&g_cursor[d], 1);
    g_csr[p] = src[i];
}

// ---------------- tf32 GEMM (dual weights): yl = X @ W0^T, yr = X @ W1^T ----------------
__device__ __forceinline__ uint32_t f2tf32(float x) {
    uint32_t u;
    asm("cvt.rna.tf32.f32 %0, %1;" : "=r"(u) : "f"(x));
    return u;
}

__device__ __forceinline__ void mma_tf32(float* c, const uint32_t* a, uint32_t b0, uint32_t b1) {
    asm volatile(
        "mma.sync.aligned.m16n8k8.row.col.f32.tf32.tf32.f32 "
        "{%0,%1,%2,%3}, {%4,%5,%6,%7}, {%8,%9}, {%0,%1,%2,%3};"
        : "+f"(c[0]), "+f"(c[1]), "+f"(c[2]), "+f"(c[3])
        : "r"(a[0]), "r"(a[1]), "r"(a[2]), "r"(a[3]), "r"(b0), "r"(b1));
}

// BM=64 rows/block, K=128 in 8 chunks of BK=16, double-buffered A and W in smem.
// 256 threads = 8 warps arranged 2(M) x 4(N); warp tile 32 x (CT/4).
// CT = 2C columns total ([W0 | W1]); warps wn<2 write yl, wn>=2 write yr.
template <int C>
__global__ void __launch_bounds__(256, 2) gemm_dual(const float* __restrict__ Xin,
                                                    const float* __restrict__ W0,
                                                    const float* __restrict__ W1,
                                                    int M, int insel) {
    constexpr int CT  = 2 * C;
    constexpr int WN  = CT / 4;   // cols per warp
    constexpr int NT  = WN / 8;   // n8 tiles per warp
    constexpr int WL4 = CT / 64;  // float4 W loads per thread per chunk
    constexpr int APITCH = 20;    // padded row pitch (conflict-free for frag loads)
    constexpr int ASZ = 64 * APITCH;

    extern __shared__ uint32_t smem[];
    uint32_t* As = smem;            // 2 * 64*20
    uint32_t* Ws = smem + 2 * ASZ;  // 2 * CT*20

    const float* X = (insel == 0) ? Xin : (insel == 1 ? g_h1 : g_h2);

    const int tid  = threadIdx.x;
    const int lane = tid & 31;
    const int wid  = tid >> 5;
    const int wm   = wid & 1;
    const int wn   = wid >> 1;
    const int row0 = blockIdx.x * 64;

    const int ar = tid >> 2;   // 0..63 : A row / W base row
    const int aq = tid & 3;    // float4 index within 16-wide chunk
    const int agr = row0 + ar;
    const bool aval = agr < M;
    const float4* Arow = (const float4*)(X + (size_t)(aval ? agr : 0) * KDIM);

    const float4* Wrow[WL4];
#pragma unroll
    for (int i = 0; i < WL4; i++) {
        int n = ar + i * 64;
        Wrow[i] = (const float4*)((n < C) ? (W0 + n * KDIM) : (W1 + (n - C) * KDIM));
    }

    float acc[2][NT][4];
#pragma unroll
    for (int mt = 0; mt < 2; mt++)
#pragma unroll
        for (int nt = 0; nt < NT; nt++)
#pragma unroll
            for (int q = 0; q < 4; q++) acc[mt][nt][q] = 0.0f;

    // preload chunk 0
    float4 aR = aval ? Arow[aq] : make_float4(0.f, 0.f, 0.f, 0.f);
    float4 wR[WL4];
#pragma unroll
    for (int i = 0; i < WL4; i++) wR[i] = Wrow[i][aq];

    {   // store chunk 0 into buffer 0
        uint4 u = make_uint4(f2tf32(aR.x), f2tf32(aR.y), f2tf32(aR.z), f2tf32(aR.w));
        *(uint4*)&As[ar * APITCH + aq * 4] = u;
#pragma unroll
        for (int i = 0; i < WL4; i++) {
            uint4 w = make_uint4(f2tf32(wR[i].x), f2tf32(wR[i].y), f2tf32(wR[i].z), f2tf32(wR[i].w));
            *(uint4*)&Ws[(ar + i * 64) * APITCH + aq * 4] = w;
        }
    }
    __syncthreads();

    const int lr = lane >> 2;  // fragment row-within-8
    const int lc = lane & 3;   // fragment k-within-4

#pragma unroll
    for (int ch = 0; ch < 8; ch++) {
        const int buf = ch & 1;
        if (ch < 7) {
            aR = aval ? Arow[(ch + 1) * 4 + aq] : make_float4(0.f, 0.f, 0.f, 0.f);
#pragma unroll
            for (int i = 0; i < WL4; i++) wR[i] = Wrow[i][(ch + 1) * 4 + aq];
        }
        const uint32_t* Ab = As + buf * ASZ;
        const uint32_t* Wb = Ws + buf * CT * APITCH;
#pragma unroll
        for (int s = 0; s < 2; s++) {
            const int ko = s * 8;
            uint32_t a[2][4];
#pragma unroll
            for (int mt = 0; mt < 2; mt++) {
                int r = wm * 32 + mt * 16 + lr;
                a[mt][0] = Ab[r * APITCH + ko + lc];
                a[mt][1] = Ab[(r + 8) * APITCH + ko + lc];
                a[mt][2] = Ab[r * APITCH + ko + lc + 4];
                a[mt][3] = Ab[(r + 8) * APITCH + ko + lc + 4];
            }
#pragma unroll
            for (int nt = 0; nt < NT; nt++) {
                int nr = wn * WN + nt * 8 + lr;
                uint32_t b0 = Wb[nr * APITCH + ko + lc];
                uint32_t b1 = Wb[nr * APITCH + ko + lc + 4];
                mma_tf32(acc[0][nt], a[0], b0, b1);
                mma_tf32(acc[1][nt], a[1], b0, b1);
            }
        }
        if (ch < 7) {
            __syncthreads();
            uint32_t* An = As + (buf ^ 1) * ASZ;
            uint32_t* Wn = Ws + (buf ^ 1) * CT * APITCH;
            uint4 u = make_uint4(f2tf32(aR.x), f2tf32(aR.y), f2tf32(aR.z), f2tf32(aR.w));
            *(uint4*)&An[ar * APITCH + aq * 4] = u;
#pragma unroll
            for (int i = 0; i < WL4; i++) {
                uint4 w = make_uint4(f2tf32(wR[i].x), f2tf32(wR[i].y), f2tf32(wR[i].z), f2tf32(wR[i].w));
                *(uint4*)&Wn[(ar + i * 64) * APITCH + aq * 4] = w;
            }
            __syncthreads();
        }
    }

    // epilogue: write yl (wn<2) or yr (wn>=2)
    float* Y = (wn < 2) ? g_yl : g_yr;
    const int cb = (wn & 1) * WN;
#pragma unroll
    for (int mt = 0; mt < 2; mt++) {
        int r = row0 + wm * 32 + mt * 16 + lr;
#pragma unroll
        for (int nt = 0; nt < NT; nt++) {
            int cc = cb + nt * 8 + 2 * lc;
            if (r < M) {
                float2 v = make_float2(acc[mt][nt][0], acc[mt][nt][1]);
                *(float2*)(Y + r * C + cc) = v;
            }
            if (r + 8 < M) {
                float2 v = make_float2(acc[mt][nt][2], acc[mt][nt][3]);
                *(float2*)(Y + (r + 8) * C + cc) = v;
            }
        }
    }
}

// ---------------- aggregation + BN + ReLU (C=128), one warp per node ----------------
__global__ void __launch_bounds__(256) agg_bn_relu(const float* __restrict__ b,
                                                   const float* __restrict__ g,
                                                   const float* __restrict__ be,
                                                   const float* __restrict__ rm,
                                                   const float* __restrict__ rv,
                                                   int which) {
    __shared__ float sc[128], sh[128], sb[128];
    int tid = threadIdx.x;
    if (tid < 128) {
        float s = g[tid] * rsqrtf(rv[tid] + 1e-5f);
        sc[tid] = s;
        sh[tid] = be[tid] - rm[tid] * s;
        sb[tid] = b[tid];
    }
    __syncthreads();

    int node = blockIdx.x * 8 + (tid >> 5);
    if (node >= NNODES) return;
    int lane = tid & 31;

    const float4* ylp = (const float4*)g_yl;
    int j = g_rowstart[node];
    int e = j + g_deg[node];

    float4 acc = make_float4(0.f, 0.f, 0.f, 0.f);
    for (; j + 4 <= e; j += 4) {
        int i0 = g_csr[j], i1 = g_csr[j + 1], i2 = g_csr[j + 2], i3 = g_csr[j + 3];
        float4 v0 = ylp[i0 * 32 + lane];
        float4 v1 = ylp[i1 * 32 + lane];
        float4 v2 = ylp[i2 * 32 + lane];
        float4 v3 = ylp[i3 * 32 + lane];
        acc.x += (v0.x + v1.x) + (v2.x + v3.x);
        acc.y += (v0.y + v1.y) + (v2.y + v3.y);
        acc.z += (v0.z + v1.z) + (v2.z + v3.z);
        acc.w += (v0.w + v1.w) + (v2.w + v3.w);
    }
    for (; j < e; j++) {
        float4 v = ylp[g_csr[j] * 32 + lane];
        acc.x += v.x; acc.y += v.y; acc.z += v.z; acc.w += v.w;
    }

    float inv = g_invdeg[node];
    float4 yr4 = ((const float4*)g_yr)[node * 32 + lane];
    int f = lane * 4;
    float4 o;
    float v;
    v = fmaf(acc.x, inv, sb[f + 0] + yr4.x); o.x = fmaxf(0.f, fmaf(v, sc[f + 0], sh[f + 0]));
    v = fmaf(acc.y, inv, sb[f + 1] + yr4.y); o.y = fmaxf(0.f, fmaf(v, sc[f + 1], sh[f + 1]));
    v = fmaf(acc.z, inv, sb[f + 2] + yr4.z); o.z = fmaxf(0.f, fmaf(v, sc[f + 2], sh[f + 2]));
    v = fmaf(acc.w, inv, sb[f + 3] + yr4.w); o.w = fmaxf(0.f, fmaf(v, sc[f + 3], sh[f + 3]));

    float* hout = which ? g_h2 : g_h1;
    ((float4*)hout)[node * 32 + lane] = o;
}

// ---------------- aggregation + log_softmax (C=64), one warp per node ----------------
__global__ void __launch_bounds__(256) agg_lsm(const float* __restrict__ b3,
                                               float* __restrict__ out) {
    int tid = threadIdx.x;
    int node = blockIdx.x * 8 + (tid >> 5);
    if (node >= NNODES) return;
    int lane = tid & 31;

    const float2* ylp = (const float2*)g_yl;
    int j = g_rowstart[node];
    int e = j + g_deg[node];

    float2 acc = make_float2(0.f, 0.f);
    for (; j + 4 <= e; j += 4) {
        int i0 = g_csr[j], i1 = g_csr[j + 1], i2 = g_csr[j + 2], i3 = g_csr[j + 3];
        float2 v0 = ylp[i0 * 32 + lane];
        float2 v1 = ylp[i1 * 32 + lane];
        float2 v2 = ylp[i2 * 32 + lane];
        float2 v3 = ylp[i3 * 32 + lane];
        acc.x += (v0.x + v1.x) + (v2.x + v3.x);
        acc.y += (v0.y + v1.y) + (v2.y + v3.y);
    }
    for (; j < e; j++) {
        float2 v = ylp[g_csr[j] * 32 + lane];
        acc.x += v.x; acc.y += v.y;
    }

    float inv = g_invdeg[node];
    float2 yr2 = ((const float2*)g_yr)[node * 32 + lane];
    int f = lane * 2;
    float v0 = fmaf(acc.x, inv, __ldg(&b3[f + 0]) + yr2.x);
    float v1 = fmaf(acc.y, inv, __ldg(&b3[f + 1]) + yr2.y);

    float m = fmaxf(v0, v1);
#pragma unroll
    for (int o = 16; o > 0; o >>= 1) m = fmaxf(m, __shfl_xor_sync(0xffffffffu, m, o));
    float s = expf(v0 - m) + expf(v1 - m);
#pragma unroll
    for (int o = 16; o > 0; o >>= 1) s += __shfl_xor_sync(0xffffffffu, s, o);
    float l = m + logf(s);

    ((float2*)out)[node * 32 + lane] = make_float2(v0 - l, v1 - l);
}

// ---------------- launch ----------------
extern "C" void kernel_launch(void* const* d_in, const int* in_sizes, int n_in,
                              void* d_out, int out_size) {
    const float* x   = (const float*)d_in[0];
    const int*   src = (const int*)d_in[1];
    const int*   dst = (const int*)d_in[2];
    const float* W1l = (const float*)d_in[3];
    const float* W1r = (const float*)d_in[4];
    const float* b1  = (const float*)d_in[5];
    const float* g1  = (const float*)d_in[6];
    const float* be1 = (const float*)d_in[7];
    const float* rm1 = (const float*)d_in[8];
    const float* rv1 = (const float*)d_in[9];
    const float* W2l = (const float*)d_in[10];
    const float* W2r = (const float*)d_in[11];
    const float* b2  = (const float*)d_in[12];
    const float* g2  = (const float*)d_in[13];
    const float* be2 = (const float*)d_in[14];
    const float* rm2 = (const float*)d_in[15];
    const float* rv2 = (const float*)d_in[16];
    const float* W3l = (const float*)d_in[17];
    const float* W3r = (const float*)d_in[18];
    const float* b3  = (const float*)d_in[19];
    float* out = (float*)d_out;

    cudaFuncSetAttribute(gemm_dual<128>, cudaFuncAttributeMaxDynamicSharedMemorySize, 51200);
    cudaFuncSetAttribute(gemm_dual<64>,  cudaFuncAttributeMaxDynamicSharedMemorySize, 30720);

    const int nblk_scan = (NNODES + 1023) / 1024;  // 98

    zero_deg_kernel<<<(NNODES + 255) / 256, 256>>>();
    count_deg_kernel<<<(NEDGES + 255) / 256, 256>>>(dst);
    scan1_kernel<<<nblk_scan, 256>>>();
    scan2_kernel<<<1, 128>>>(nblk_scan);
    scan3_kernel<<<(NNODES + 255) / 256, 256>>>();
    fill_csr_kernel<<<(NEDGES + 255) / 256, 256>>>(src, dst);

    const int gemm_grid = (NNODES + 63) / 64;   // 1563
    const int agg_grid  = (NNODES + 7) / 8;     // 12500

    // layer 1
    gemm_dual<128><<<gemm_grid, 256, 51200>>>(x, W1l, W1r, NNODES, 0);
    agg_bn_relu<<<agg_grid, 256>>>(b1, g1, be1, rm1, rv1, 0);
    // layer 2
    gemm_dual<128><<<gemm_grid, 256, 51200>>>(nullptr, W2l, W2r, NNODES, 1);
    agg_bn_relu<<<agg_grid, 256>>>(b2, g2, be2, rm2, rv2, 1);
    // layer 3
    gemm_dual<64><<<gemm_grid, 256, 30720>>>(nullptr, W3l, W3r, NNODES, 2);
    agg_lsm<<<agg_grid, 256>>>(b3, out);
}

// round 6
// speedup vs baseline: 1.0292x; 1.0292x over previous
#include <cuda_runtime.h>
#include <cuda_bf16.h>
#include <cstdint>
#include <math.h>

#define NNODES 100000
#define NEDGES 1600000
#define KDIM   128

// ---------------- device scratch (no allocations allowed) ----------------
__device__ int   g_deg[NNODES];
__device__ int   g_rowstart[NNODES];
__device__ int   g_cursor[NNODES];
__device__ float g_invdeg[NNODES];
__device__ int   g_blocksum[128];
__device__ int   g_blockoff[128];
__device__ int   g_csr[NEDGES];
__device__ __nv_bfloat16 g_ylb[(size_t)NNODES * 128];
__device__ __nv_bfloat16 g_yrb[(size_t)NNODES * 128];
__device__ float g_h1[(size_t)NNODES * 128];
__device__ float g_h2[(size_t)NNODES * 128];

// ---------------- CSR build ----------------
__global__ void zero_deg_kernel() {
    int i = blockIdx.x * blockDim.x + threadIdx.x;
    if (i < NNODES) g_deg[i] = 0;
}

__global__ void count_deg_kernel(const int* __restrict__ dst) {
    int i = blockIdx.x * blockDim.x + threadIdx.x;
    if (i < NEDGES) atomicAdd(&g_deg[dst[i]], 1);
}

// block scans 1024 elems (256 thr x 4); inclusive partials -> g_rowstart,
// block total -> g_blocksum.
__global__ void scan1_kernel() {
    __shared__ int sdata[256];
    int b = blockIdx.x, t = threadIdx.x;
    int base = b * 1024 + t * 4;
    int v0 = (base + 0 < NNODES) ? g_deg[base + 0] : 0;
    int v1 = (base + 1 < NNODES) ? g_deg[base + 1] : 0;
    int v2 = (base + 2 < NNODES) ? g_deg[base + 2] : 0;
    int v3 = (base + 3 < NNODES) ? g_deg[base + 3] : 0;
    int tsum = v0 + v1 + v2 + v3;
    sdata[t] = tsum;
    __syncthreads();
    for (int off = 1; off < 256; off <<= 1) {
        int x = (t >= off) ? sdata[t - off] : 0;
        __syncthreads();
        sdata[t] += x;
        __syncthreads();
    }
    int excl = sdata[t] - tsum;
    int r0 = excl + v0, r1 = r0 + v1, r2 = r1 + v2, r3 = r2 + v3;
    if (base + 0 < NNODES) g_rowstart[base + 0] = r0;
    if (base + 1 < NNODES) g_rowstart[base + 1] = r1;
    if (base + 2 < NNODES) g_rowstart[base + 2] = r2;
    if (base + 3 < NNODES) g_rowstart[base + 3] = r3;
    if (t == 255) g_blocksum[b] = sdata[255];
}

__global__ void scan2_kernel(int nb) {
    __shared__ int sdata[128];
    int t = threadIdx.x;
    int v = (t < nb) ? g_blocksum[t] : 0;
    sdata[t] = v;
    __syncthreads();
    for (int off = 1; off < 128; off <<= 1) {
        int x = (t >= off) ? sdata[t - off] : 0;
        __syncthreads();
        sdata[t] += x;
        __syncthreads();
    }
    g_blockoff[t] = sdata[t] - v;   // exclusive
}

__global__ void scan3_kernel() {
    int i = blockIdx.x * blockDim.x + threadIdx.x;
    if (i >= NNODES) return;
    int incl = g_rowstart[i];
    int d = g_deg[i];
    int start = incl - d + g_blockoff[i >> 10];
    g_rowstart[i] = start;
    g_cursor[i] = start;
    g_invdeg[i] = 1.0f / (float)max(d, 1);
}

__global__ void fill_csr_kernel(const int* __restrict__ src, const int* __restrict__ dst) {
    int i = blockIdx.x * blockDim.x + threadIdx.x;
    if (i >= NEDGES) return;
    int d = dst[i];
    int p = atomicAdd(&g_cursor[d], 1);
    g_csr[p] = src[i];
}

// ---------------- tf32 GEMM (dual weights): yl = X @ W0^T, yr = X @ W1^T ----------------
__device__ __forceinline__ uint32_t f2tf32(float x) {
    uint32_t u;
    asm("cvt.rna.tf32.f32 %0, %1;" : "=r"(u) : "f"(x));
    return u;
}

__device__ __forceinline__ void mma_tf32(float* c, const uint32_t* a, uint32_t b0, uint32_t b1) {
    asm volatile(
        "mma.sync.aligned.m16n8k8.row.col.f32.tf32.tf32.f32 "
        "{%0,%1,%2,%3}, {%4,%5,%6,%7}, {%8,%9}, {%0,%1,%2,%3};"
        : "+f"(c[0]), "+f"(c[1]), "+f"(c[2]), "+f"(c[3])
        : "r"(a[0]), "r"(a[1]), "r"(a[2]), "r"(a[3]), "r"(b0), "r"(b1));
}

// BM=64 rows/block, K=128 in 8 chunks of BK=16, double-buffered A and W in smem.
// 256 threads = 8 warps arranged 2(M) x 4(N); CT = 2C cols ([W0 | W1]);
// warps wn<2 write yl (bf16), wn>=2 write yr (bf16).
template <int C>
__global__ void __launch_bounds__(256, 2) gemm_dual(const float* __restrict__ Xin,
                                                    const float* __restrict__ W0,
                                                    const float* __restrict__ W1,
                                                    int M, int insel) {
    constexpr int CT  = 2 * C;
    constexpr int WN  = CT / 4;   // cols per warp
    constexpr int NT  = WN / 8;   // n8 tiles per warp
    constexpr int WL4 = CT / 64;  // float4 W loads per thread per chunk
    constexpr int APITCH = 20;    // padded row pitch (conflict-free)
    constexpr int ASZ = 64 * APITCH;

    extern __shared__ uint32_t smem[];
    uint32_t* As = smem;            // 2 * 64*20
    uint32_t* Ws = smem + 2 * ASZ;  // 2 * CT*20

    const float* X = (insel == 0) ? Xin : (insel == 1 ? g_h1 : g_h2);

    const int tid  = threadIdx.x;
    const int lane = tid & 31;
    const int wid  = tid >> 5;
    const int wm   = wid & 1;
    const int wn   = wid >> 1;
    const int row0 = blockIdx.x * 64;

    const int ar = tid >> 2;   // 0..63
    const int aq = tid & 3;
    const int agr = row0 + ar;
    const bool aval = agr < M;
    const float4* Arow = (const float4*)(X + (size_t)(aval ? agr : 0) * KDIM);

    const float4* Wrow[WL4];
#pragma unroll
    for (int i = 0; i < WL4; i++) {
        int n = ar + i * 64;
        Wrow[i] = (const float4*)((n < C) ? (W0 + n * KDIM) : (W1 + (n - C) * KDIM));
    }

    float acc[2][NT][4];
#pragma unroll
    for (int mt = 0; mt < 2; mt++)
#pragma unroll
        for (int nt = 0; nt < NT; nt++)
#pragma unroll
            for (int q = 0; q < 4; q++) acc[mt][nt][q] = 0.0f;

    // preload chunk 0
    float4 aR = aval ? Arow[aq] : make_float4(0.f, 0.f, 0.f, 0.f);
    float4 wR[WL4];
#pragma unroll
    for (int i = 0; i < WL4; i++) wR[i] = Wrow[i][aq];

    {
        uint4 u = make_uint4(f2tf32(aR.x), f2tf32(aR.y), f2tf32(aR.z), f2tf32(aR.w));
        *(uint4*)&As[ar * APITCH + aq * 4] = u;
#pragma unroll
        for (int i = 0; i < WL4; i++) {
            uint4 w = make_uint4(f2tf32(wR[i].x), f2tf32(wR[i].y), f2tf32(wR[i].z), f2tf32(wR[i].w));
            *(uint4*)&Ws[(ar + i * 64) * APITCH + aq * 4] = w;
        }
    }
    __syncthreads();

    const int lr = lane >> 2;
    const int lc = lane & 3;

#pragma unroll
    for (int ch = 0; ch < 8; ch++) {
        const int buf = ch & 1;
        if (ch < 7) {
            aR = aval ? Arow[(ch + 1) * 4 + aq] : make_float4(0.f, 0.f, 0.f, 0.f);
#pragma unroll
            for (int i = 0; i < WL4; i++) wR[i] = Wrow[i][(ch + 1) * 4 + aq];
        }
        const uint32_t* Ab = As + buf * ASZ;
        const uint32_t* Wb = Ws + buf * CT * APITCH;
#pragma unroll
        for (int s = 0; s < 2; s++) {
            const int ko = s * 8;
            uint32_t a[2][4];
#pragma unroll
            for (int mt = 0; mt < 2; mt++) {
                int r = wm * 32 + mt * 16 + lr;
                a[mt][0] = Ab[r * APITCH + ko + lc];
                a[mt][1] = Ab[(r + 8) * APITCH + ko + lc];
                a[mt][2] = Ab[r * APITCH + ko + lc + 4];
                a[mt][3] = Ab[(r + 8) * APITCH + ko + lc + 4];
            }
#pragma unroll
            for (int nt = 0; nt < NT; nt++) {
                int nr = wn * WN + nt * 8 + lr;
                uint32_t b0 = Wb[nr * APITCH + ko + lc];
                uint32_t b1 = Wb[nr * APITCH + ko + lc + 4];
                mma_tf32(acc[0][nt], a[0], b0, b1);
                mma_tf32(acc[1][nt], a[1], b0, b1);
            }
        }
        if (ch < 7) {
            __syncthreads();
            uint32_t* An = As + (buf ^ 1) * ASZ;
            uint32_t* Wn = Ws + (buf ^ 1) * CT * APITCH;
            uint4 u = make_uint4(f2tf32(aR.x), f2tf32(aR.y), f2tf32(aR.z), f2tf32(aR.w));
            *(uint4*)&An[ar * APITCH + aq * 4] = u;
#pragma unroll
            for (int i = 0; i < WL4; i++) {
                uint4 w = make_uint4(f2tf32(wR[i].x), f2tf32(wR[i].y), f2tf32(wR[i].z), f2tf32(wR[i].w));
                *(uint4*)&Wn[(ar + i * 64) * APITCH + aq * 4] = w;
            }
            __syncthreads();
        }
    }

    // epilogue: pack to bf16; yl (wn<2) or yr (wn>=2)
    __nv_bfloat16* Y = (wn < 2) ? g_ylb : g_yrb;
    const int cb = (wn & 1) * WN;
#pragma unroll
    for (int mt = 0; mt < 2; mt++) {
        int r = row0 + wm * 32 + mt * 16 + lr;
#pragma unroll
        for (int nt = 0; nt < NT; nt++) {
            int cc = cb + nt * 8 + 2 * lc;
            if (r < M) {
                __nv_bfloat162 v = __floats2bfloat162_rn(acc[mt][nt][0], acc[mt][nt][1]);
                *(__nv_bfloat162*)(Y + r * C + cc) = v;
            }
            if (r + 8 < M) {
                __nv_bfloat162 v = __floats2bfloat162_rn(acc[mt][nt][2], acc[mt][nt][3]);
                *(__nv_bfloat162*)(Y + (r + 8) * C + cc) = v;
            }
        }
    }
}

// ---------------- aggregation + BN + ReLU (C=128), one warp per node ----------------
__global__ void __launch_bounds__(256) agg_bn_relu(const float* __restrict__ b,
                                                   const float* __restrict__ g,
                                                   const float* __restrict__ be,
                                                   const float* __restrict__ rm,
                                                   const float* __restrict__ rv,
                                                   int which) {
    __shared__ float sc[128], sh[128], sb[128];
    int tid = threadIdx.x;
    if (tid < 128) {
        float s = g[tid] * rsqrtf(rv[tid] + 1e-5f);
        sc[tid] = s;
        sh[tid] = be[tid] - rm[tid] * s;
        sb[tid] = b[tid];
    }
    __syncthreads();

    int node = blockIdx.x * 8 + (tid >> 5);
    if (node >= NNODES) return;
    int lane = tid & 31;

    const uint2* ylp = (const uint2*)g_ylb;   // row = 32 uint2 (128 bf16)
    int j = g_rowstart[node];
    int e = j + g_deg[node];

    float4 acc = make_float4(0.f, 0.f, 0.f, 0.f);
    for (; j + 4 <= e; j += 4) {
        int i0 = g_csr[j], i1 = g_csr[j + 1], i2 = g_csr[j + 2], i3 = g_csr[j + 3];
        uint2 u0 = ylp[i0 * 32 + lane];
        uint2 u1 = ylp[i1 * 32 + lane];
        uint2 u2 = ylp[i2 * 32 + lane];
        uint2 u3 = ylp[i3 * 32 + lane];
        float2 a0 = __bfloat1622float2(*(const __nv_bfloat162*)&u0.x);
        float2 b0 = __bfloat1622float2(*(const __nv_bfloat162*)&u0.y);
        float2 a1 = __bfloat1622float2(*(const __nv_bfloat162*)&u1.x);
        float2 b1_ = __bfloat1622float2(*(const __nv_bfloat162*)&u1.y);
        float2 a2 = __bfloat1622float2(*(const __nv_bfloat162*)&u2.x);
        float2 b2_ = __bfloat1622float2(*(const __nv_bfloat162*)&u2.y);
        float2 a3 = __bfloat1622float2(*(const __nv_bfloat162*)&u3.x);
        float2 b3_ = __bfloat1622float2(*(const __nv_bfloat162*)&u3.y);
        acc.x += (a0.x + a1.x) + (a2.x + a3.x);
        acc.y += (a0.y + a1.y) + (a2.y + a3.y);
        acc.z += (b0.x + b1_.x) + (b2_.x + b3_.x);
        acc.w += (b0.y + b1_.y) + (b2_.y + b3_.y);
    }
    for (; j < e; j++) {
        uint2 u = ylp[g_csr[j] * 32 + lane];
        float2 a = __bfloat1622float2(*(const __nv_bfloat162*)&u.x);
        float2 bq = __bfloat1622float2(*(const __nv_bfloat162*)&u.y);
        acc.x += a.x; acc.y += a.y; acc.z += bq.x; acc.w += bq.y;
    }

    float inv = g_invdeg[node];
    uint2 yru = ((const uint2*)g_yrb)[node * 32 + lane];
    float2 yra = __bfloat1622float2(*(const __nv_bfloat162*)&yru.x);
    float2 yrb = __bfloat1622float2(*(const __nv_bfloat162*)&yru.y);
    int f = lane * 4;
    float4 o;
    float v;
    v = fmaf(acc.x, inv, sb[f + 0] + yra.x); o.x = fmaxf(0.f, fmaf(v, sc[f + 0], sh[f + 0]));
    v = fmaf(acc.y, inv, sb[f + 1] + yra.y); o.y = fmaxf(0.f, fmaf(v, sc[f + 1], sh[f + 1]));
    v = fmaf(acc.z, inv, sb[f + 2] + yrb.x); o.z = fmaxf(0.f, fmaf(v, sc[f + 2], sh[f + 2]));
    v = fmaf(acc.w, inv, sb[f + 3] + yrb.y); o.w = fmaxf(0.f, fmaf(v, sc[f + 3], sh[f + 3]));

    float* hout = which ? g_h2 : g_h1;
    ((float4*)hout)[node * 32 + lane] = o;
}

// ---------------- aggregation + log_softmax (C=64), one warp per node ----------------
__global__ void __launch_bounds__(256) agg_lsm(const float* __restrict__ b3,
                                               float* __restrict__ out) {
    int tid = threadIdx.x;
    int node = blockIdx.x * 8 + (tid >> 5);
    if (node >= NNODES) return;
    int lane = tid & 31;

    const __nv_bfloat162* ylp = (const __nv_bfloat162*)g_ylb;  // row = 32 bf16x2
    int j = g_rowstart[node];
    int e = j + g_deg[node];

    float2 acc = make_float2(0.f, 0.f);
    for (; j + 4 <= e; j += 4) {
        int i0 = g_csr[j], i1 = g_csr[j + 1], i2 = g_csr[j + 2], i3 = g_csr[j + 3];
        float2 v0 = __bfloat1622float2(ylp[i0 * 32 + lane]);
        float2 v1 = __bfloat1622float2(ylp[i1 * 32 + lane]);
        float2 v2 = __bfloat1622float2(ylp[i2 * 32 + lane]);
        float2 v3 = __bfloat1622float2(ylp[i3 * 32 + lane]);
        acc.x += (v0.x + v1.x) + (v2.x + v3.x);
        acc.y += (v0.y + v1.y) + (v2.y + v3.y);
    }
    for (; j < e; j++) {
        float2 v = __bfloat1622float2(ylp[g_csr[j] * 32 + lane]);
        acc.x += v.x; acc.y += v.y;
    }

    float inv = g_invdeg[node];
    float2 yr2 = __bfloat1622float2(((const __nv_bfloat162*)g_yrb)[node * 32 + lane]);
    int f = lane * 2;
    float v0 = fmaf(acc.x, inv, __ldg(&b3[f + 0]) + yr2.x);
    float v1 = fmaf(acc.y, inv, __ldg(&b3[f + 1]) + yr2.y);

    float m = fmaxf(v0, v1);
#pragma unroll
    for (int o = 16; o > 0; o >>= 1) m = fmaxf(m, __shfl_xor_sync(0xffffffffu, m, o));
    float s = expf(v0 - m) + expf(v1 - m);
#pragma unroll
    for (int o = 16; o > 0; o >>= 1) s += __shfl_xor_sync(0xffffffffu, s, o);
    float l = m + logf(s);

    ((float2*)out)[node * 32 + lane] = make_float2(v0 - l, v1 - l);
}

// ---------------- launch ----------------
extern "C" void kernel_launch(void* const* d_in, const int* in_sizes, int n_in,
                              void* d_out, int out_size) {
    const float* x   = (const float*)d_in[0];
    const int*   src = (const int*)d_in[1];
    const int*   dst = (const int*)d_in[2];
    const float* W1l = (const float*)d_in[3];
    const float* W1r = (const float*)d_in[4];
    const float* b1  = (const float*)d_in[5];
    const float* g1  = (const float*)d_in[6];
    const float* be1 = (const float*)d_in[7];
    const float* rm1 = (const float*)d_in[8];
    const float* rv1 = (const float*)d_in[9];
    const float* W2l = (const float*)d_in[10];
    const float* W2r = (const float*)d_in[11];
    const float* b2  = (const float*)d_in[12];
    const float* g2  = (const float*)d_in[13];
    const float* be2 = (const float*)d_in[14];
    const float* rm2 = (const float*)d_in[15];
    const float* rv2 = (const float*)d_in[16];
    const float* W3l = (const float*)d_in[17];
    const float* W3r = (const float*)d_in[18];
    const float* b3  = (const float*)d_in[19];
    float* out = (float*)d_out;

    cudaFuncSetAttribute(gemm_dual<128>, cudaFuncAttributeMaxDynamicSharedMemorySize, 51200);
    cudaFuncSetAttribute(gemm_dual<64>,  cudaFuncAttributeMaxDynamicSharedMemorySize, 30720);

    const int nblk_scan = (NNODES + 1023) / 1024;  // 98

    zero_deg_kernel<<<(NNODES + 255) / 256, 256>>>();
    count_deg_kernel<<<(NEDGES + 255) / 256, 256>>>(dst);
    scan1_kernel<<<nblk_scan, 256>>>();
    scan2_kernel<<<1, 128>>>(nblk_scan);
    scan3_kernel<<<(NNODES + 255) / 256, 256>>>();
    fill_csr_kernel<<<(NEDGES + 255) / 256, 256>>>(src, dst);

    const int gemm_grid = (NNODES + 63) / 64;   // 1563
    const int agg_grid  = (NNODES + 7) / 8;     // 12500

    // layer 1
    gemm_dual<128><<<gemm_grid, 256, 51200>>>(x, W1l, W1r, NNODES, 0);
    agg_bn_relu<<<agg_grid, 256>>>(b1, g1, be1, rm1, rv1, 0);
    // layer 2
    gemm_dual<128><<<gemm_grid, 256, 51200>>>(nullptr, W2l, W2r, NNODES, 1);
    agg_bn_relu<<<agg_grid, 256>>>(b2, g2, be2, rm2, rv2, 1);
    // layer 3
    gemm_dual<64><<<gemm_grid, 256, 30720>>>(nullptr, W3l, W3r, NNODES, 2);
    agg_lsm<<<agg_grid, 256>>>(b3, out);
}

// round 7
// speedup vs baseline: 1.3382x; 1.3002x over previous
#include <cuda_runtime.h>
#include <cuda_bf16.h>
#include <cstdint>
#include <math.h>

#define NNODES 100000
#define NEDGES 1600000
#define KDIM   128

// weight buffer offsets (elements) in g_wb
#define OFF_W1L 0
#define OFF_W1R 16384
#define OFF_W2L 32768
#define OFF_W2R 49152
#define OFF_W3L 65536
#define OFF_W3R 73728
#define WB_TOTAL 81920

// ---------------- device scratch (no allocations allowed) ----------------
__device__ int   g_deg[NNODES];
__device__ int   g_rowstart[NNODES];
__device__ int   g_cursor[NNODES];
__device__ float g_invdeg[NNODES];
__device__ int   g_blocksum[128];
__device__ int   g_csr[NEDGES];
__device__ __nv_bfloat16 g_wb[WB_TOTAL];
__device__ __nv_bfloat16 g_ylb[(size_t)NNODES * 128];
__device__ __nv_bfloat16 g_yrb[(size_t)NNODES * 128];
__device__ __nv_bfloat16 g_h1b[(size_t)NNODES * 128];
__device__ __nv_bfloat16 g_h2b[(size_t)NNODES * 128];

// ---------------- weight conversion (fp32 -> bf16, once per launch) ----------------
__global__ void prep_w(const float* __restrict__ W1l, const float* __restrict__ W1r,
                       const float* __restrict__ W2l, const float* __restrict__ W2r,
                       const float* __restrict__ W3l, const float* __restrict__ W3r) {
    int i = blockIdx.x * blockDim.x + threadIdx.x;
    if (i >= WB_TOTAL) return;
    float v;
    if      (i < OFF_W1R) v = W1l[i - OFF_W1L];
    else if (i < OFF_W2L) v = W1r[i - OFF_W1R];
    else if (i < OFF_W2R) v = W2l[i - OFF_W2L];
    else if (i < OFF_W3L) v = W2r[i - OFF_W2R];
    else if (i < OFF_W3R) v = W3l[i - OFF_W3L];
    else                  v = W3r[i - OFF_W3R];
    g_wb[i] = __float2bfloat16(v);
}

// ---------------- CSR build ----------------
__global__ void count_deg_kernel(const int* __restrict__ dst) {
    int i = blockIdx.x * blockDim.x + threadIdx.x;
    if (i < NEDGES) atomicAdd(&g_deg[dst[i]], 1);
}

// block scans 1024 elems (256 thr x 4); inclusive partials -> g_rowstart,
// block total -> g_blocksum.
__global__ void scan1_kernel() {
    __shared__ int sdata[256];
    int b = blockIdx.x, t = threadIdx.x;
    int base = b * 1024 + t * 4;
    int v0 = (base + 0 < NNODES) ? g_deg[base + 0] : 0;
    int v1 = (base + 1 < NNODES) ? g_deg[base + 1] : 0;
    int v2 = (base + 2 < NNODES) ? g_deg[base + 2] : 0;
    int v3 = (base + 3 < NNODES) ? g_deg[base + 3] : 0;
    int tsum = v0 + v1 + v2 + v3;
    sdata[t] = tsum;
    __syncthreads();
    for (int off = 1; off < 256; off <<= 1) {
        int x = (t >= off) ? sdata[t - off] : 0;
        __syncthreads();
        sdata[t] += x;
        __syncthreads();
    }
    int excl = sdata[t] - tsum;
    int r0 = excl + v0, r1 = r0 + v1, r2 = r1 + v2, r3 = r2 + v3;
    if (base + 0 < NNODES) g_rowstart[base + 0] = r0;
    if (base + 1 < NNODES) g_rowstart[base + 1] = r1;
    if (base + 2 < NNODES) g_rowstart[base + 2] = r2;
    if (base + 3 < NNODES) g_rowstart[base + 3] = r3;
    if (t == 255) g_blocksum[b] = sdata[255];
}

// fused: per-block redundant exclusive scan of blocksums + rowstart/cursor/invdeg finalize
__global__ void scan23_kernel(int nb) {
    __shared__ int sdat[128], sexc[128];
    int t = threadIdx.x;
    int v = 0;
    if (t < 128) { v = (t < nb) ? g_blocksum[t] : 0; sdat[t] = v; }
    __syncthreads();
    for (int off = 1; off < 128; off <<= 1) {
        int x = 0;
        if (t < 128 && t >= off) x = sdat[t - off];
        __syncthreads();
        if (t < 128) sdat[t] += x;
        __syncthreads();
    }
    if (t < 128) sexc[t] = sdat[t] - v;
    __syncthreads();
    int i = blockIdx.x * blockDim.x + t;
    if (i >= NNODES) return;
    int incl = g_rowstart[i];
    int d = g_deg[i];
    int start = incl - d + sexc[i >> 10];
    g_rowstart[i] = start;
    g_cursor[i] = start;
    g_invdeg[i] = 1.0f / (float)max(d, 1);
}

__global__ void fill_csr_kernel(const int* __restrict__ src, const int* __restrict__ dst) {
    int i = blockIdx.x * blockDim.x + threadIdx.x;
    if (i >= NEDGES) return;
    int d = dst[i];
    int p = atomicAdd(&g_cursor[d], 1);
    g_csr[p] = src[i];
}

// ---------------- bf16 GEMM (dual weights): yl = X @ W0^T, yr = X @ W1^T ----------------
__device__ __forceinline__ uint32_t pack_bf2(float a, float b) {
    __nv_bfloat162 p = __floats2bfloat162_rn(a, b);
    return *(uint32_t*)&p;
}

__device__ __forceinline__ void mma_bf16(float* c, const uint32_t* a, uint32_t b0, uint32_t b1) {
    asm volatile(
        "mma.sync.aligned.m16n8k16.row.col.f32.bf16.bf16.f32 "
        "{%0,%1,%2,%3}, {%4,%5,%6,%7}, {%8,%9}, {%0,%1,%2,%3};"
        : "+f"(c[0]), "+f"(c[1]), "+f"(c[2]), "+f"(c[3])
        : "r"(a[0]), "r"(a[1]), "r"(a[2]), "r"(a[3]), "r"(b0), "r"(b1));
}

// BM=64 rows/block, K=128 in 4 chunks of 32 (bf16 pairs: 16 uint32/row/chunk),
// double-buffered A and W in smem via cp.async. 256 threads = 8 warps (2M x 4N).
// CT = 2C cols ([W0 | W1]); warps wn<2 write yl, wn>=2 write yr (bf16).
template <int C, bool AF32>
__global__ void __launch_bounds__(256, 2) gemm_dual(const float* __restrict__ Xf,
                                                    int insel, int w0off, int w1off, int M) {
    constexpr int CT = 2 * C;
    constexpr int WN = CT / 4;    // cols per warp
    constexpr int NT = WN / 8;    // n8 tiles per warp
    constexpr int WL = CT / 64;   // uint4 W loads per thread per chunk
    constexpr int P  = 20;        // row pitch in uint32 (conflict-free)
    constexpr int ASZ = 64 * P;
    constexpr int WSZ = CT * P;

    extern __shared__ uint32_t smem[];
    uint32_t* As = smem;            // 2 * ASZ
    uint32_t* Ws = smem + 2 * ASZ;  // 2 * WSZ

    const __nv_bfloat16* W0 = g_wb + w0off;
    const __nv_bfloat16* W1 = g_wb + w1off;
    const __nv_bfloat16* Xb = (insel == 1) ? g_h1b : g_h2b;

    const int tid  = threadIdx.x;
    const int lane = tid & 31;
    const int wid  = tid >> 5;
    const int wm   = wid & 1;
    const int wn   = wid >> 1;
    const int row0 = blockIdx.x * 64;

    const int ar = tid >> 2;   // 0..63
    const int aq = tid & 3;
    const int agr = row0 + ar;
    const int arow_c = (agr < M) ? agr : 0;

    const uint4* Wr[WL];
#pragma unroll
    for (int i = 0; i < WL; i++) {
        int n = ar + i * 64;
        Wr[i] = (const uint4*)((n < C) ? (W0 + n * KDIM) : (W1 + (n - C) * KDIM));
    }
    const float4* Af  = (const float4*)(Xf + (size_t)arow_c * KDIM);
    const uint4*  Ab4 = (const uint4*)(Xb + (size_t)arow_c * KDIM);

    float acc[2][NT][4];
#pragma unroll
    for (int mt = 0; mt < 2; mt++)
#pragma unroll
        for (int nt = 0; nt < NT; nt++)
#pragma unroll
            for (int q = 0; q < 4; q++) acc[mt][nt][q] = 0.0f;

    auto issue = [&](int ch, int buf) {
        // A chunk: 16B per thread
        if (AF32) {
            float4 f0 = Af[ch * 8 + aq * 2];
            float4 f1 = Af[ch * 8 + aq * 2 + 1];
            uint4 u;
            u.x = pack_bf2(f0.x, f0.y); u.y = pack_bf2(f0.z, f0.w);
            u.z = pack_bf2(f1.x, f1.y); u.w = pack_bf2(f1.z, f1.w);
            *(uint4*)&As[buf * ASZ + ar * P + aq * 4] = u;
        } else {
            uint32_t adst = (uint32_t)__cvta_generic_to_shared(&As[buf * ASZ + ar * P + aq * 4]);
            asm volatile("cp.async.cg.shared.global [%0], [%1], 16;"
                         :: "r"(adst), "l"(Ab4 + ch * 4 + aq));
        }
        // W chunk: WL x 16B per thread
#pragma unroll
        for (int i = 0; i < WL; i++) {
            uint32_t wdst = (uint32_t)__cvta_generic_to_shared(
                &Ws[buf * WSZ + (ar + i * 64) * P + aq * 4]);
            asm volatile("cp.async.cg.shared.global [%0], [%1], 16;"
                         :: "r"(wdst), "l"(Wr[i] + ch * 4 + aq));
        }
    };

    issue(0, 0);
    asm volatile("cp.async.commit_group;");

    const int lr = lane >> 2;
    const int lc = lane & 3;

#pragma unroll
    for (int ch = 0; ch < 4; ch++) {
        if (ch < 3) {
            issue(ch + 1, (ch + 1) & 1);
            asm volatile("cp.async.commit_group;");
            asm volatile("cp.async.wait_group 1;");
        } else {
            asm volatile("cp.async.wait_group 0;");
        }
        __syncthreads();

        const uint32_t* Abuf = As + (ch & 1) * ASZ;
        const uint32_t* Wbuf = Ws + (ch & 1) * WSZ;
#pragma unroll
        for (int s = 0; s < 2; s++) {
            const int ko = s * 8;
            uint32_t a[2][4];
#pragma unroll
            for (int mt = 0; mt < 2; mt++) {
                int r = wm * 32 + mt * 16 + lr;
                a[mt][0] = Abuf[r * P + ko + lc];
                a[mt][1] = Abuf[(r + 8) * P + ko + lc];
                a[mt][2] = Abuf[r * P + ko + lc + 4];
                a[mt][3] = Abuf[(r + 8) * P + ko + lc + 4];
            }
#pragma unroll
            for (int nt = 0; nt < NT; nt++) {
                int nr = wn * WN + nt * 8 + lr;
                uint32_t b0 = Wbuf[nr * P + ko + lc];
                uint32_t b1 = Wbuf[nr * P + ko + lc + 4];
                mma_bf16(acc[0][nt], a[0], b0, b1);
                mma_bf16(acc[1][nt], a[1], b0, b1);
            }
        }
        __syncthreads();
    }

    // epilogue: pack to bf16; yl (wn<2) or yr (wn>=2)
    __nv_bfloat16* Y = (wn < 2) ? g_ylb : g_yrb;
    const int cb = (wn & 1) * WN;
#pragma unroll
    for (int mt = 0; mt < 2; mt++) {
        int r = row0 + wm * 32 + mt * 16 + lr;
#pragma unroll
        for (int nt = 0; nt < NT; nt++) {
            int cc = cb + nt * 8 + 2 * lc;
            if (r < M) {
                uint32_t v = pack_bf2(acc[mt][nt][0], acc[mt][nt][1]);
                *(uint32_t*)(Y + r * C + cc) = v;
            }
            if (r + 8 < M) {
                uint32_t v = pack_bf2(acc[mt][nt][2], acc[mt][nt][3]);
                *(uint32_t*)(Y + (r + 8) * C + cc) = v;
            }
        }
    }
}

// ---------------- aggregation + BN + ReLU (C=128), one warp per node ----------------
__global__ void __launch_bounds__(256) agg_bn_relu(const float* __restrict__ b,
                                                   const float* __restrict__ g,
                                                   const float* __restrict__ be,
                                                   const float* __restrict__ rm,
                                                   const float* __restrict__ rv,
                                                   int which) {
    __shared__ float sc[128], sh[128], sb[128];
    int tid = threadIdx.x;
    if (tid < 128) {
        float s = g[tid] * rsqrtf(rv[tid] + 1e-5f);
        sc[tid] = s;
        sh[tid] = be[tid] - rm[tid] * s;
        sb[tid] = b[tid];
    }
    __syncthreads();

    int node = blockIdx.x * 8 + (tid >> 5);
    if (node >= NNODES) return;
    int lane = tid & 31;

    const uint2* ylp = (const uint2*)g_ylb;   // row = 32 uint2 (128 bf16)
    int j = g_rowstart[node];
    int e = j + g_deg[node];

    float4 acc = make_float4(0.f, 0.f, 0.f, 0.f);
    for (; j + 4 <= e; j += 4) {
        int i0 = g_csr[j], i1 = g_csr[j + 1], i2 = g_csr[j + 2], i3 = g_csr[j + 3];
        uint2 u0 = ylp[i0 * 32 + lane];
        uint2 u1 = ylp[i1 * 32 + lane];
        uint2 u2 = ylp[i2 * 32 + lane];
        uint2 u3 = ylp[i3 * 32 + lane];
        float2 a0 = __bfloat1622float2(*(const __nv_bfloat162*)&u0.x);
        float2 b0 = __bfloat1622float2(*(const __nv_bfloat162*)&u0.y);
        float2 a1 = __bfloat1622float2(*(const __nv_bfloat162*)&u1.x);
        float2 b1_ = __bfloat1622float2(*(const __nv_bfloat162*)&u1.y);
        float2 a2 = __bfloat1622float2(*(const __nv_bfloat162*)&u2.x);
        float2 b2_ = __bfloat1622float2(*(const __nv_bfloat162*)&u2.y);
        float2 a3 = __bfloat1622float2(*(const __nv_bfloat162*)&u3.x);
        float2 b3_ = __bfloat1622float2(*(const __nv_bfloat162*)&u3.y);
        acc.x += (a0.x + a1.x) + (a2.x + a3.x);
        acc.y += (a0.y + a1.y) + (a2.y + a3.y);
        acc.z += (b0.x + b1_.x) + (b2_.x + b3_.x);
        acc.w += (b0.y + b1_.y) + (b2_.y + b3_.y);
    }
    for (; j < e; j++) {
        uint2 u = ylp[g_csr[j] * 32 + lane];
        float2 a = __bfloat1622float2(*(const __nv_bfloat162*)&u.x);
        float2 bq = __bfloat1622float2(*(const __nv_bfloat162*)&u.y);
        acc.x += a.x; acc.y += a.y; acc.z += bq.x; acc.w += bq.y;
    }

    float inv = g_invdeg[node];
    uint2 yru = ((const uint2*)g_yrb)[node * 32 + lane];
    float2 yra = __bfloat1622float2(*(const __nv_bfloat162*)&yru.x);
    float2 yrb = __bfloat1622float2(*(const __nv_bfloat162*)&yru.y);
    int f = lane * 4;
    float4 o;
    float v;
    v = fmaf(acc.x, inv, sb[f + 0] + yra.x); o.x = fmaxf(0.f, fmaf(v, sc[f + 0], sh[f + 0]));
    v = fmaf(acc.y, inv, sb[f + 1] + yra.y); o.y = fmaxf(0.f, fmaf(v, sc[f + 1], sh[f + 1]));
    v = fmaf(acc.z, inv, sb[f + 2] + yrb.x); o.z = fmaxf(0.f, fmaf(v, sc[f + 2], sh[f + 2]));
    v = fmaf(acc.w, inv, sb[f + 3] + yrb.y); o.w = fmaxf(0.f, fmaf(v, sc[f + 3], sh[f + 3]));

    __nv_bfloat16* hout = which ? g_h2b : g_h1b;
    uint2 st;
    st.x = pack_bf2(o.x, o.y);
    st.y = pack_bf2(o.z, o.w);
    ((uint2*)hout)[node * 32 + lane] = st;
}

// ---------------- aggregation + log_softmax (C=64), one warp per node ----------------
__global__ void __launch_bounds__(256) agg_lsm(const float* __restrict__ b3,
                                               float* __restrict__ out) {
    int tid = threadIdx.x;
    int node = blockIdx.x * 8 + (tid >> 5);
    if (node >= NNODES) return;
    int lane = tid & 31;

    const __nv_bfloat162* ylp = (const __nv_bfloat162*)g_ylb;  // row = 32 bf16x2
    int j = g_rowstart[node];
    int e = j + g_deg[node];

    float2 acc = make_float2(0.f, 0.f);
    for (; j + 4 <= e; j += 4) {
        int i0 = g_csr[j], i1 = g_csr[j + 1], i2 = g_csr[j + 2], i3 = g_csr[j + 3];
        float2 v0 = __bfloat1622float2(ylp[i0 * 32 + lane]);
        float2 v1 = __bfloat1622float2(ylp[i1 * 32 + lane]);
        float2 v2 = __bfloat1622float2(ylp[i2 * 32 + lane]);
        float2 v3 = __bfloat1622float2(ylp[i3 * 32 + lane]);
        acc.x += (v0.x + v1.x) + (v2.x + v3.x);
        acc.y += (v0.y + v1.y) + (v2.y + v3.y);
    }
    for (; j < e; j++) {
        float2 v = __bfloat1622float2(ylp[g_csr[j] * 32 + lane]);
        acc.x += v.x; acc.y += v.y;
    }

    float inv = g_invdeg[node];
    float2 yr2 = __bfloat1622float2(((const __nv_bfloat162*)g_yrb)[node * 32 + lane]);
    int f = lane * 2;
    float v0 = fmaf(acc.x, inv, __ldg(&b3[f + 0]) + yr2.x);
    float v1 = fmaf(acc.y, inv, __ldg(&b3[f + 1]) + yr2.y);

    float m = fmaxf(v0, v1);
#pragma unroll
    for (int o = 16; o > 0; o >>= 1) m = fmaxf(m, __shfl_xor_sync(0xffffffffu, m, o));
    float s = expf(v0 - m) + expf(v1 - m);
#pragma unroll
    for (int o = 16; o > 0; o >>= 1) s += __shfl_xor_sync(0xffffffffu, s, o);
    float l = m + logf(s);

    ((float2*)out)[node * 32 + lane] = make_float2(v0 - l, v1 - l);
}

// ---------------- launch ----------------
extern "C" void kernel_launch(void* const* d_in, const int* in_sizes, int n_in,
                              void* d_out, int out_size) {
    const float* x   = (const float*)d_in[0];
    const int*   src = (const int*)d_in[1];
    const int*   dst = (const int*)d_in[2];
    const float* W1l = (const float*)d_in[3];
    const float* W1r = (const float*)d_in[4];
    const float* b1  = (const float*)d_in[5];
    const float* g1  = (const float*)d_in[6];
    const float* be1 = (const float*)d_in[7];
    const float* rm1 = (const float*)d_in[8];
    const float* rv1 = (const float*)d_in[9];
    const float* W2l = (const float*)d_in[10];
    const float* W2r = (const float*)d_in[11];
    const float* b2  = (const float*)d_in[12];
    const float* g2  = (const float*)d_in[13];
    const float* be2 = (const float*)d_in[14];
    const float* rm2 = (const float*)d_in[15];
    const float* rv2 = (const float*)d_in[16];
    const float* W3l = (const float*)d_in[17];
    const float* W3r = (const float*)d_in[18];
    const float* b3  = (const float*)d_in[19];
    float* out = (float*)d_out;

    cudaFuncSetAttribute(gemm_dual<128, true>,  cudaFuncAttributeMaxDynamicSharedMemorySize, 51200);
    cudaFuncSetAttribute(gemm_dual<128, false>, cudaFuncAttributeMaxDynamicSharedMemorySize, 51200);
    cudaFuncSetAttribute(gemm_dual<64,  false>, cudaFuncAttributeMaxDynamicSharedMemorySize, 30720);

    const int nblk_scan = (NNODES + 1023) / 1024;  // 98

    void* degp = nullptr;
    cudaGetSymbolAddress(&degp, g_deg);
    cudaMemsetAsync(degp, 0, NNODES * sizeof(int));

    prep_w<<<(WB_TOTAL + 255) / 256, 256>>>(W1l, W1r, W2l, W2r, W3l, W3r);
    count_deg_kernel<<<(NEDGES + 255) / 256, 256>>>(dst);
    scan1_kernel<<<nblk_scan, 256>>>();
    scan23_kernel<<<(NNODES + 255) / 256, 256>>>(nblk_scan);
    fill_csr_kernel<<<(NEDGES + 255) / 256, 256>>>(src, dst);

    const int gemm_grid = (NNODES + 63) / 64;   // 1563
    const int agg_grid  = (NNODES + 7) / 8;     // 12500

    // layer 1
    gemm_dual<128, true><<<gemm_grid, 256, 51200>>>(x, 0, OFF_W1L, OFF_W1R, NNODES);
    agg_bn_relu<<<agg_grid, 256>>>(b1, g1, be1, rm1, rv1, 0);
    // layer 2
    gemm_dual<128, false><<<gemm_grid, 256, 51200>>>(nullptr, 1, OFF_W2L, OFF_W2R, NNODES);
    agg_bn_relu<<<agg_grid, 256>>>(b2, g2, be2, rm2, rv2, 1);
    // layer 3
    gemm_dual<64, false><<<gemm_grid, 256, 30720>>>(nullptr, 2, OFF_W3L, OFF_W3R, NNODES);
    agg_lsm<<<agg_grid, 256>>>(b3, out);
}